// round 2
// baseline (speedup 1.0000x reference)
#include <cuda_runtime.h>

#define NB   16
#define CIN  512
#define COUT 512
#define SDIM 512
#define HH   64
#define WW   64

#define TCO 32   // couts per block
#define CC  16   // cin chunk

// 1/sqrt(512), 1/sqrt(512*9)
#define MOD_SCALE  0.04419417382415922f
#define CONV_SCALE 0.014731391274719742f

// scratch (device globals — no allocation allowed)
__device__ float g_s[NB * CIN];       // CONV_SCALE * (style @ modW^T + bias)
__device__ float g_wsq[COUT * CIN];   // sum over 3x3 of weight^2
__device__ float g_demod[NB * COUT];

// ---------------- s[b,ci] = CONV_SCALE*(sum_d style[b,d]*modW[ci,d]*MOD_SCALE + bias[ci])
__global__ void k_style(const float* __restrict__ style,
                        const float* __restrict__ mw,
                        const float* __restrict__ mb) {
    int w    = blockIdx.x * (blockDim.x >> 5) + (threadIdx.x >> 5);
    int lane = threadIdx.x & 31;
    int b  = w / CIN;
    int ci = w - b * CIN;
    const float* sp = style + b * SDIM;
    const float* wp = mw + ci * SDIM;
    float sum = 0.f;
    for (int d = lane; d < SDIM; d += 32) sum += sp[d] * wp[d];
    #pragma unroll
    for (int o = 16; o; o >>= 1) sum += __shfl_xor_sync(0xffffffffu, sum, o);
    if (lane == 0) g_s[w] = CONV_SCALE * (sum * MOD_SCALE + mb[ci]);
}

// ---------------- wsq[co,ci] = sum_k weight[co,ci,k]^2
__global__ void k_wsq(const float* __restrict__ wgt) {
    int i = blockIdx.x * blockDim.x + threadIdx.x;
    if (i >= COUT * CIN) return;
    const float* p = wgt + i * 9;
    float s = 0.f;
    #pragma unroll
    for (int j = 0; j < 9; ++j) s += p[j] * p[j];
    g_wsq[i] = s;
}

// ---------------- demod[b,co] = rsqrt(sum_ci wsq[co,ci]*g_s[b,ci]^2 + eps)
// (g_s already carries CONV_SCALE, so CONV_SCALE^2 is implicit in g_s^2)
__global__ void k_demod() {
    int w    = blockIdx.x * (blockDim.x >> 5) + (threadIdx.x >> 5);
    int lane = threadIdx.x & 31;
    int b  = w / COUT;
    int co = w - b * COUT;
    const float* wsq = g_wsq + co * CIN;
    const float* sp  = g_s + b * CIN;
    float sum = 0.f;
    for (int ci = lane; ci < CIN; ci += 32) {
        float sv = sp[ci];
        sum += wsq[ci] * sv * sv;
    }
    #pragma unroll
    for (int o = 16; o; o >>= 1) sum += __shfl_xor_sync(0xffffffffu, sum, o);
    if (lane == 0) g_demod[w] = rsqrtf(sum + 1e-8f);
}

// ---------------- conv: out[b,co,y,x] = demod[b,co] * sum_{ci,kh,kw} W[co,ci,kh,kw]
//                        * (g_s[b,ci] * x[b,ci,y+kh-1,x+kw-1])
// Block: 32 couts x 16x16 pixels. Thread: 8 couts x 4 pixels (32 acc).
__global__ __launch_bounds__(256, 2)
void k_conv(const float* __restrict__ x,
            const float* __restrict__ wgt,
            float* __restrict__ out) {
    __shared__ float sx[CC][18][20];      // [ci][y][x] zero-padded halo, pad-20 row
    __shared__ float sw[CC][9][TCO];      // [ci][k][co]
    __shared__ float ssc[CC];

    const int tid   = threadIdx.x;
    const int b     = blockIdx.z;
    const int co0   = blockIdx.y * TCO;
    const int tileY = (blockIdx.x >> 2) * 16;
    const int tileX = (blockIdx.x & 3) * 16;

    const int cg  = tid >> 6;        // 0..3  : cout group (8 couts)
    const int pg  = tid & 63;        // 0..63 : pixel group (4 pixels)
    const int py  = pg >> 2;         // 0..15
    const int px0 = (pg & 3) << 2;   // 0,4,8,12

    float acc[8][4];
    #pragma unroll
    for (int c = 0; c < 8; ++c)
        #pragma unroll
        for (int p = 0; p < 4; ++p) acc[c][p] = 0.f;

    for (int ci0 = 0; ci0 < CIN; ci0 += CC) {
        __syncthreads();   // guard previous compute before overwriting tiles
        if (tid < CC) ssc[tid] = g_s[b * CIN + ci0 + tid];
        __syncthreads();

        // load scaled x tile (with halo, zero-padded at image borders)
        for (int i = tid; i < CC * 18 * 18; i += 256) {
            int ci  = i / 324;
            int rem = i - ci * 324;
            int r = rem / 18;
            int c = rem - r * 18;
            int gy = tileY + r - 1;
            int gx = tileX + c - 1;
            float v = 0.f;
            if ((unsigned)gy < 64u && (unsigned)gx < 64u)
                v = x[(((b * CIN) + ci0 + ci) * 64 + gy) * 64 + gx] * ssc[ci];
            sx[ci][r][c] = v;
        }
        // load weight tile: per co-row, 144 contiguous floats (ci-chunk x 9)
        for (int i = tid; i < TCO * CC * 9; i += 256) {
            int co = i / (CC * 9);
            int r  = i - co * (CC * 9);
            int ci = r / 9;
            int k  = r - ci * 9;
            sw[ci][k][co] = wgt[((co0 + co) * CIN + ci0) * 9 + r];
        }
        __syncthreads();

        for (int ci = 0; ci < CC; ++ci) {
            float xr[3][6];
            #pragma unroll
            for (int r = 0; r < 3; ++r) {
                float4 v4 = *(const float4*)&sx[ci][py + r][px0];
                float2 v2 = *(const float2*)&sx[ci][py + r][px0 + 4];
                xr[r][0] = v4.x; xr[r][1] = v4.y; xr[r][2] = v4.z;
                xr[r][3] = v4.w; xr[r][4] = v2.x; xr[r][5] = v2.y;
            }
            #pragma unroll
            for (int k = 0; k < 9; ++k) {
                const int kh = k / 3, kw = k - kh * 3;
                float4 wa = *(const float4*)&sw[ci][k][cg * 8];
                float4 wb = *(const float4*)&sw[ci][k][cg * 8 + 4];
                float wr[8] = {wa.x, wa.y, wa.z, wa.w, wb.x, wb.y, wb.z, wb.w};
                #pragma unroll
                for (int c = 0; c < 8; ++c)
                    #pragma unroll
                    for (int p = 0; p < 4; ++p)
                        acc[c][p] += wr[c] * xr[kh][kw + p];
            }
        }
    }

    // epilogue: apply demod, vectorized store
    #pragma unroll
    for (int c = 0; c < 8; ++c) {
        int oc   = co0 + cg * 8 + c;
        float dm = g_demod[b * COUT + oc];
        float4 v;
        v.x = acc[c][0] * dm; v.y = acc[c][1] * dm;
        v.z = acc[c][2] * dm; v.w = acc[c][3] * dm;
        *(float4*)&out[((b * COUT + oc) * 64 + tileY + py) * 64 + tileX + px0] = v;
    }
}

extern "C" void kernel_launch(void* const* d_in, const int* in_sizes, int n_in,
                              void* d_out, int out_size) {
    const float* x     = (const float*)d_in[0];  // [16,512,64,64]
    const float* style = (const float*)d_in[1];  // [16,512]
    const float* wgt   = (const float*)d_in[2];  // [1,512,512,3,3]
    const float* mw    = (const float*)d_in[3];  // [512,512]
    const float* mb    = (const float*)d_in[4];  // [512]
    float* out = (float*)d_out;                  // [16,512,64,64]

    k_style<<<NB * CIN / 8, 256>>>(style, mw, mb);
    k_wsq<<<(COUT * CIN + 255) / 256, 256>>>(wgt);
    k_demod<<<NB * COUT / 8, 256>>>();

    dim3 grid(16, COUT / TCO, NB);   // (4x4 spatial tiles, 16 cout tiles, 16 batch)
    k_conv<<<grid, 256>>>(x, wgt, out);
}

// round 5
// speedup vs baseline: 2.9833x; 2.9833x over previous
#include <cuda_runtime.h>
#include <cstdint>

#define NB   16
#define CIN  512
#define COUT 512
#define SDIM 512

#define MOD_SCALE  0.04419417382415922f
#define CONV_SCALE 0.014731391274719742f

#define PW 66
#define PPLANE (PW*PW)        // 4356
#define KTOT 4608             // CIN*9
#define NCHUNK 144            // KTOT/32

// ---------------- scratch (device globals; no allocations allowed) ----------
__device__ float g_s[NB * CIN];
__device__ float g_wsq[COUT * CIN];
__device__ float g_demod[NB * COUT];
__device__ float g_xp[NB * CIN * PPLANE];   // padded, scaled, tf32-rounded input
__device__ float g_wr[COUT * KTOT];         // weights reordered [co][k*512+ci], tf32

// ======================= helpers ============================================
__device__ __forceinline__ float to_tf32(float x) {
    float y;
    asm("cvt.rna.tf32.f32 %0, %1;" : "=f"(y) : "f"(x));
    return y;
}
__device__ __forceinline__ uint32_t smem_u32(const void* p) {
    uint32_t a;
    asm("{ .reg .u64 t; cvta.to.shared.u64 t, %1; cvt.u32.u64 %0, t; }"
        : "=r"(a) : "l"(p));
    return a;
}
__device__ __forceinline__ void ldsm4(uint32_t* r, uint32_t addr) {
    asm volatile("ldmatrix.sync.aligned.m8n8.x4.shared.b16 {%0,%1,%2,%3}, [%4];"
                 : "=r"(r[0]), "=r"(r[1]), "=r"(r[2]), "=r"(r[3]) : "r"(addr));
}
__device__ __forceinline__ void mma8(float* d, const uint32_t* a,
                                     uint32_t b0, uint32_t b1) {
    asm volatile(
        "mma.sync.aligned.m16n8k8.row.col.f32.tf32.tf32.f32 "
        "{%0,%1,%2,%3}, {%4,%5,%6,%7}, {%8,%9}, {%0,%1,%2,%3};"
        : "+f"(d[0]), "+f"(d[1]), "+f"(d[2]), "+f"(d[3])
        : "r"(a[0]), "r"(a[1]), "r"(a[2]), "r"(a[3]), "r"(b0), "r"(b1));
}
__device__ __forceinline__ void sts128(uint32_t a, float x, float y, float z, float w) {
    asm volatile("st.shared.v4.f32 [%0], {%1,%2,%3,%4};"
                 :: "r"(a), "f"(x), "f"(y), "f"(z), "f"(w) : "memory");
}
__device__ __forceinline__ void cp16(uint32_t dst, const void* src) {
    asm volatile("cp.async.cg.shared.global [%0], [%1], 16;"
                 :: "r"(dst), "l"(src) : "memory");
}
#define CP_COMMIT() asm volatile("cp.async.commit_group;" ::: "memory")
#define CP_WAIT0()  asm volatile("cp.async.wait_group 0;" ::: "memory")

// ======================= prep kernels =======================================
__global__ void k_style(const float* __restrict__ style,
                        const float* __restrict__ mw,
                        const float* __restrict__ mb) {
    int w    = blockIdx.x * (blockDim.x >> 5) + (threadIdx.x >> 5);
    int lane = threadIdx.x & 31;
    int b  = w / CIN;
    int ci = w - b * CIN;
    const float* sp = style + b * SDIM;
    const float* wp = mw + ci * SDIM;
    float sum = 0.f;
    for (int d = lane; d < SDIM; d += 32) sum += sp[d] * wp[d];
    #pragma unroll
    for (int o = 16; o; o >>= 1) sum += __shfl_xor_sync(0xffffffffu, sum, o);
    if (lane == 0) g_s[w] = CONV_SCALE * (sum * MOD_SCALE + mb[ci]);
}

__global__ void k_wsq(const float* __restrict__ wgt) {
    int i = blockIdx.x * blockDim.x + threadIdx.x;
    if (i >= COUT * CIN) return;
    const float* p = wgt + i * 9;
    float s = 0.f;
    #pragma unroll
    for (int j = 0; j < 9; ++j) s += p[j] * p[j];
    g_wsq[i] = s;
}

__global__ void k_demod() {
    int w    = blockIdx.x * (blockDim.x >> 5) + (threadIdx.x >> 5);
    int lane = threadIdx.x & 31;
    int b  = w / COUT;
    int co = w - b * COUT;
    const float* wsq = g_wsq + co * CIN;
    const float* sp  = g_s + b * CIN;
    float sum = 0.f;
    for (int ci = lane; ci < CIN; ci += 32) {
        float sv = sp[ci];
        sum += wsq[ci] * sv * sv;
    }
    #pragma unroll
    for (int o = 16; o; o >>= 1) sum += __shfl_xor_sync(0xffffffffu, sum, o);
    if (lane == 0) g_demod[w] = rsqrtf(sum + 1e-8f);
}

// padded, scaled, tf32-rounded input
__global__ void k_pad(const float* __restrict__ x) {
    int plane = blockIdx.x;                // b*512 + ci
    float s = g_s[plane];
    const float* xs = x + (size_t)plane * 4096;
    float* xd = g_xp + (size_t)plane * PPLANE;
    for (int i = threadIdx.x; i < PPLANE; i += 256) {
        int py = i / PW;
        int px = i - py * PW;
        float v = 0.f;
        if ((unsigned)(py - 1) < 64u && (unsigned)(px - 1) < 64u)
            v = to_tf32(xs[(py - 1) * 64 + (px - 1)] * s);
        xd[i] = v;
    }
}

// g_wr[co][k*512 + ci] = tf32(W[co][ci][k])
__global__ void k_wr(const float* __restrict__ w) {
    int i = blockIdx.x * blockDim.x + threadIdx.x;
    if (i >= COUT * KTOT) return;
    int co = i / KTOT;
    int kk = i - co * KTOT;
    int k  = kk >> 9;
    int ci = kk & 511;
    g_wr[i] = to_tf32(w[(co * 512 + ci) * 9 + k]);
}

// ======================= main conv kernel ===================================
// CTA: 512 thr / 16 warps.  Tile M=128 co x N=256 px.  Warp tile 64x32 (2x8).
// K = 4608 in 144 chunks of 32 (tap x 32 cin).  Double-buffered SMEM:
// A[co=128][k=32] (16KB) and B[px=256][k=32] (32KB), 128B rows, XOR-16B swizzle.
#define SM_A0 0
#define SM_A1 16384
#define SM_B0 32768
#define SM_B1 65536
#define SM_TOTAL 98304

__global__ __launch_bounds__(512, 1)
void k_conv(float* __restrict__ out) {
    extern __shared__ char smem[];
    const uint32_t sbase = smem_u32(smem);
    const int tid  = threadIdx.x;
    const int wid  = tid >> 5;
    const int lane = tid & 31;
    const int b    = blockIdx.z;
    const int co0  = blockIdx.y * 128;
    const int p0   = blockIdx.x * 256;   // 4 full image rows
    const int y0   = p0 >> 6;

    const int wm = wid >> 3;             // 0..1  -> co offset wm*64
    const int wn = wid & 7;              // 0..7  -> px offset wn*32

    // ldmatrix per-thread row/kgroup mapping
    const int r7     = lane & 7;
    const int a_row  = r7 + (((lane >> 3) & 1) << 3);
    const int a_kga  = lane >> 4;
    const int b_row  = r7 + (((lane >> 4) & 1) << 3);
    const int b_kga  = (lane >> 3) & 1;
    const uint32_t aoff = (uint32_t)(wm * 64 + a_row) * 128;
    const uint32_t boff = (uint32_t)(wn * 32 + b_row) * 128;

    const float* xpb = g_xp + (size_t)b * CIN * PPLANE;

    float acc[4][4][4];
    #pragma unroll
    for (int i = 0; i < 4; ++i)
        #pragma unroll
        for (int j = 0; j < 4; ++j)
            #pragma unroll
            for (int h = 0; h < 4; ++h) acc[i][j][h] = 0.f;

    // ---- chunk helpers (inline) ----
    auto cpA = [&](int c) {
        uint32_t An = sbase + ((c & 1) ? SM_A1 : SM_A0);
        #pragma unroll
        for (int j = 0; j < 2; ++j) {
            int G   = tid + j * 512;
            int row = G >> 3;
            int c4  = G & 7;
            const float* src = g_wr + (size_t)(co0 + row) * KTOT + (c << 5) + (c4 << 2);
            cp16(An + row * 128 + (((uint32_t)(c4 ^ (row & 7))) << 4), src);
        }
        CP_COMMIT();
    };
    auto ldB = [&](int c, float* r) {
        int k   = c >> 4;
        int kh  = k / 3;
        int kw  = k - 3 * kh;
        int ci0 = (c & 15) << 5;
        int xoff = (y0 + kh) * PW + kw;
        #pragma unroll
        for (int j = 0; j < 4; ++j) {
            int G  = tid + j * 512;
            int px = G & 255;
            int c4 = G >> 8;
            const float* bp = xpb + (size_t)(ci0 + (c4 << 2)) * PPLANE
                            + xoff + (px >> 6) * PW + (px & 63);
            r[4 * j + 0] = bp[0];
            r[4 * j + 1] = bp[PPLANE];
            r[4 * j + 2] = bp[2 * PPLANE];
            r[4 * j + 3] = bp[3 * PPLANE];
        }
    };
    auto stsB = [&](int c, const float* r) {
        uint32_t Bn = sbase + ((c & 1) ? SM_B1 : SM_B0);
        #pragma unroll
        for (int j = 0; j < 4; ++j) {
            int G  = tid + j * 512;
            int px = G & 255;
            int c4 = G >> 8;
            sts128(Bn + px * 128 + (((uint32_t)(c4 ^ (px & 7))) << 4),
                   r[4 * j], r[4 * j + 1], r[4 * j + 2], r[4 * j + 3]);
        }
    };

    // ---- prologue: chunk 0 ----
    {
        cpA(0);
        float rB[16];
        ldB(0, rB);
        stsB(0, rB);
        CP_WAIT0();
        __syncthreads();
    }

    // ---- main loop ----
    for (int c = 0; c < NCHUNK; ++c) {
        float rB[16];
        const bool more = (c + 1 < NCHUNK);
        if (more) { cpA(c + 1); ldB(c + 1, rB); }

        const uint32_t Ab = sbase + ((c & 1) ? SM_A1 : SM_A0);
        const uint32_t Bb = sbase + ((c & 1) ? SM_B1 : SM_B0);

        #pragma unroll
        for (int ks = 0; ks < 4; ++ks) {
            uint32_t af[4][4];
            const uint32_t asw = ((uint32_t)((2 * ks + a_kga) ^ r7)) << 4;
            #pragma unroll
            for (int mt = 0; mt < 4; ++mt)
                ldsm4(af[mt], Ab + aoff + mt * 2048 + asw);

            uint32_t bf[2][4];
            const uint32_t bsw = ((uint32_t)((2 * ks + b_kga) ^ r7)) << 4;
            #pragma unroll
            for (int np = 0; np < 2; ++np)
                ldsm4(bf[np], Bb + boff + np * 2048 + bsw);

            #pragma unroll
            for (int mt = 0; mt < 4; ++mt)
                #pragma unroll
                for (int np = 0; np < 2; ++np) {
                    mma8(acc[mt][2 * np],     af[mt], bf[np][0], bf[np][1]);
                    mma8(acc[mt][2 * np + 1], af[mt], bf[np][2], bf[np][3]);
                }
        }

        if (more) { stsB(c + 1, rB); CP_WAIT0(); }
        __syncthreads();
    }

    // ---- epilogue: demod + store ----
    const int row0 = lane >> 2;
    const int colp = (lane & 3) << 1;
    #pragma unroll
    for (int mt = 0; mt < 4; ++mt) {
        #pragma unroll
        for (int h = 0; h < 2; ++h) {
            const int co = co0 + wm * 64 + mt * 16 + row0 + h * 8;
            const float dm = g_demod[b * COUT + co];
            float* op = out + (size_t)(b * COUT + co) * 4096 + p0 + wn * 32 + colp;
            #pragma unroll
            for (int nt = 0; nt < 4; ++nt) {
                float2 v;
                v.x = acc[mt][nt][2 * h + 0] * dm;
                v.y = acc[mt][nt][2 * h + 1] * dm;
                *(float2*)(op + nt * 8) = v;
            }
        }
    }
}

// ======================= launch =============================================
extern "C" void kernel_launch(void* const* d_in, const int* in_sizes, int n_in,
                              void* d_out, int out_size) {
    const float* x     = (const float*)d_in[0];  // [16,512,64,64]
    const float* style = (const float*)d_in[1];  // [16,512]
    const float* wgt   = (const float*)d_in[2];  // [1,512,512,3,3]
    const float* mw    = (const float*)d_in[3];  // [512,512]
    const float* mb    = (const float*)d_in[4];  // [512]
    float* out = (float*)d_out;                  // [16,512,64,64]

    k_style<<<NB * CIN / 8, 256>>>(style, mw, mb);
    k_wsq<<<(COUT * CIN + 255) / 256, 256>>>(wgt);
    k_demod<<<NB * COUT / 8, 256>>>();
    k_pad<<<NB * CIN, 256>>>(x);
    k_wr<<<(COUT * KTOT + 255) / 256, 256>>>(wgt);

    cudaFuncSetAttribute(k_conv, cudaFuncAttributeMaxDynamicSharedMemorySize, SM_TOTAL);
    dim3 grid(16, COUT / 128, NB);   // (16 px tiles, 4 co tiles, 16 batch)
    k_conv<<<grid, 512, SM_TOTAL>>>(out);
}

// round 6
// speedup vs baseline: 6.0527x; 2.0289x over previous
#include <cuda_runtime.h>
#include <cuda_fp16.h>
#include <cstdint>

#define NB   16
#define CIN  512
#define COUT 512
#define SDIM 512

#define MOD_SCALE  0.04419417382415922f
#define CONV_SCALE 0.014731391274719742f

#define PW 66
#define KTOT 4608             // CIN*9
#define NCHUNK 72             // K chunks of 64 (tap x 64 cin)

// ---------------- scratch (device globals; no allocations allowed) ----------
__device__ float g_s[NB * CIN];
__device__ float g_wsq[COUT * CIN];
__device__ float g_demod[NB * COUT];
// NHWC padded, scaled input, half: [b][py 66][px 66][ci 512]
__device__ __align__(16) __half g_xph[(size_t)NB * PW * PW * CIN];
// weights half, reordered [co][tap*512 + ci]
__device__ __align__(16) __half g_wrh[(size_t)COUT * KTOT];

// ======================= helpers ============================================
__device__ __forceinline__ uint32_t smem_u32(const void* p) {
    uint32_t a;
    asm("{ .reg .u64 t; cvta.to.shared.u64 t, %1; cvt.u32.u64 %0, t; }"
        : "=r"(a) : "l"(p));
    return a;
}
__device__ __forceinline__ void ldsm4(uint32_t* r, uint32_t addr) {
    asm volatile("ldmatrix.sync.aligned.m8n8.x4.shared.b16 {%0,%1,%2,%3}, [%4];"
                 : "=r"(r[0]), "=r"(r[1]), "=r"(r[2]), "=r"(r[3]) : "r"(addr));
}
__device__ __forceinline__ void mma16(float* d, const uint32_t* a,
                                      uint32_t b0, uint32_t b1) {
    asm volatile(
        "mma.sync.aligned.m16n8k16.row.col.f32.f16.f16.f32 "
        "{%0,%1,%2,%3}, {%4,%5,%6,%7}, {%8,%9}, {%0,%1,%2,%3};"
        : "+f"(d[0]), "+f"(d[1]), "+f"(d[2]), "+f"(d[3])
        : "r"(a[0]), "r"(a[1]), "r"(a[2]), "r"(a[3]), "r"(b0), "r"(b1));
}
__device__ __forceinline__ void cp16(uint32_t dst, const void* src) {
    asm volatile("cp.async.cg.shared.global [%0], [%1], 16;"
                 :: "r"(dst), "l"(src) : "memory");
}
#define CP_COMMIT() asm volatile("cp.async.commit_group;" ::: "memory")
#define CP_WAIT1()  asm volatile("cp.async.wait_group 1;" ::: "memory")

// ======================= prep kernels =======================================
__global__ void k_style(const float* __restrict__ style,
                        const float* __restrict__ mw,
                        const float* __restrict__ mb) {
    int w    = blockIdx.x * (blockDim.x >> 5) + (threadIdx.x >> 5);
    int lane = threadIdx.x & 31;
    int b  = w / CIN;
    int ci = w - b * CIN;
    const float* sp = style + b * SDIM;
    const float* wp = mw + ci * SDIM;
    float sum = 0.f;
    for (int d = lane; d < SDIM; d += 32) sum += sp[d] * wp[d];
    #pragma unroll
    for (int o = 16; o; o >>= 1) sum += __shfl_xor_sync(0xffffffffu, sum, o);
    if (lane == 0) g_s[w] = CONV_SCALE * (sum * MOD_SCALE + mb[ci]);
}

__global__ void k_wsq(const float* __restrict__ wgt) {
    int i = blockIdx.x * blockDim.x + threadIdx.x;
    if (i >= COUT * CIN) return;
    const float* p = wgt + i * 9;
    float s = 0.f;
    #pragma unroll
    for (int j = 0; j < 9; ++j) s += p[j] * p[j];
    g_wsq[i] = s;
}

__global__ void k_demod() {
    int w    = blockIdx.x * (blockDim.x >> 5) + (threadIdx.x >> 5);
    int lane = threadIdx.x & 31;
    int b  = w / COUT;
    int co = w - b * COUT;
    const float* wsq = g_wsq + co * CIN;
    const float* sp  = g_s + b * CIN;
    float sum = 0.f;
    for (int ci = lane; ci < CIN; ci += 32) {
        float sv = sp[ci];
        sum += wsq[ci] * sv * sv;
    }
    #pragma unroll
    for (int o = 16; o; o >>= 1) sum += __shfl_xor_sync(0xffffffffu, sum, o);
    if (lane == 0) g_demod[w] = rsqrtf(sum + 1e-8f);
}

// NHWC padded transpose: g_xph[b][py][px][ci] = half(x[b][ci][py-1][px-1]*s)
__global__ __launch_bounds__(256)
void k_padT(const float* __restrict__ x) {
    __shared__ float sm[64][65];
    const int b  = blockIdx.y;
    const int py = blockIdx.x;
    const int tid = threadIdx.x;
    __half* xd = g_xph + (((size_t)b * PW + py) * PW) * CIN;

    if (py == 0 || py == 65) {
        uint4 z = {0, 0, 0, 0};
        for (int i = tid; i < PW * CIN / 8; i += 256)
            ((uint4*)xd)[i] = z;
        return;
    }
    const int y = py - 1;
    // zero px=0 and px=65 columns
    for (int i = tid; i < CIN / 2; i += 256) {
        ((__half2*)xd)[i] = __half2(__float2half(0.f), __float2half(0.f));
        ((__half2*)(xd + 65 * CIN))[i] = __half2(__float2half(0.f), __float2half(0.f));
    }
    for (int ci0 = 0; ci0 < CIN; ci0 += 64) {
        __syncthreads();
        for (int i = tid; i < 64 * 64; i += 256) {
            int ci = i >> 6, px = i & 63;
            sm[ci][px] = x[(((size_t)(b * CIN + ci0 + ci) * 64) + y) * 64 + px]
                       * g_s[b * CIN + ci0 + ci];
        }
        __syncthreads();
        for (int i = tid; i < 64 * 32; i += 256) {
            int px = i >> 5, c2 = i & 31;
            __half2 h = __floats2half2_rn(sm[2 * c2][px], sm[2 * c2 + 1][px]);
            *(__half2*)(xd + (size_t)(px + 1) * CIN + ci0 + 2 * c2) = h;
        }
    }
}

// g_wrh[co][tap*512 + ci] = half(W[co][ci][tap])
__global__ void k_wrh(const float* __restrict__ w) {
    int i = blockIdx.x * blockDim.x + threadIdx.x;
    if (i >= COUT * KTOT) return;
    int co  = i / KTOT;
    int r   = i - co * KTOT;
    int tap = r >> 9;
    int ci  = r & 511;
    g_wrh[i] = __float2half_rn(w[(co * 512 + ci) * 9 + tap]);
}

// ======================= main conv kernel ===================================
// CTA 512 thr / 16 warps. Tile M=128 co x N=256 px (4 image rows).
// K = 4608 in 72 chunks of 64 (tap x 64 cin), fp16, 128B rows, XOR-16B swizzle.
// 3-stage cp.async pipeline: stage = A(16KB) + B(32KB) = 48KB, total 144KB.
#define SM_STAGE 49152
#define SM_BOFF  16384
#define SM_TOTAL (3 * SM_STAGE)

__global__ __launch_bounds__(512, 1)
void k_conv(float* __restrict__ out) {
    extern __shared__ char smem[];
    const uint32_t sbase = smem_u32(smem);
    const int tid  = threadIdx.x;
    const int wid  = tid >> 5;
    const int lane = tid & 31;
    const int b    = blockIdx.z;
    const int co0  = blockIdx.y * 128;
    const int p0   = blockIdx.x * 256;   // 4 full image rows
    const int y0   = p0 >> 6;

    const int wm = wid >> 3;             // 0..1 : co offset wm*64
    const int wn = wid & 7;              // 0..7 : px offset wn*32

    const int r7    = lane & 7;
    const int a_row = lane & 15;
    const int a_kga = lane >> 4;
    const int b_row = r7 + (((lane >> 4) & 1) << 3);
    const int b_kga = (lane >> 3) & 1;
    const uint32_t aoff = (uint32_t)(wm * 64 + a_row) * 128;
    const uint32_t boff = (uint32_t)(wn * 32 + b_row) * 128;

    const __half* xpb = g_xph + (size_t)b * PW * PW * CIN;

    float acc[4][4][4];
    #pragma unroll
    for (int i = 0; i < 4; ++i)
        #pragma unroll
        for (int j = 0; j < 4; ++j)
            #pragma unroll
            for (int h = 0; h < 4; ++h) acc[i][j][h] = 0.f;

    // issue all cp.async for chunk c into stage st
    auto issue = [&](int c, int st) {
        const uint32_t Ab = sbase + st * SM_STAGE;
        const uint32_t Bb = Ab + SM_BOFF;
        const int tap = c >> 3;
        const int kh  = tap / 3;
        const int kw  = tap - 3 * kh;
        const int ci0 = (c & 7) << 6;
        // A: 128 rows x 128B = 1024 x 16B
        #pragma unroll
        for (int j = 0; j < 2; ++j) {
            int G   = tid + j * 512;
            int row = G >> 3;
            int c4  = G & 7;
            const __half* src = g_wrh + (size_t)(co0 + row) * KTOT
                              + tap * 512 + ci0 + c4 * 8;
            cp16(Ab + row * 128 + (((uint32_t)(c4 ^ (row & 7))) << 4), src);
        }
        // B: 256 rows x 128B = 2048 x 16B
        #pragma unroll
        for (int j = 0; j < 4; ++j) {
            int G  = tid + j * 512;
            int px = G >> 3;
            int c4 = G & 7;
            const __half* src = xpb
                + ((size_t)(y0 + (px >> 6) + kh) * PW + (px & 63) + kw) * CIN
                + ci0 + c4 * 8;
            cp16(Bb + px * 128 + (((uint32_t)(c4 ^ (px & 7))) << 4), src);
        }
        CP_COMMIT();
    };

    // prologue: stages 0,1
    issue(0, 0);
    issue(1, 1);

    int st = 0;
    for (int c = 0; c < NCHUNK; ++c) {
        CP_WAIT1();          // chunk c's group complete
        __syncthreads();     // all warps done with stage we are about to refill

        if (c + 2 < NCHUNK) issue(c + 2, (st + 2 >= 3) ? st - 1 : st + 2);
        else CP_COMMIT();    // keep group accounting uniform

        const uint32_t Ab = sbase + st * SM_STAGE;
        const uint32_t Bb = Ab + SM_BOFF;

        #pragma unroll
        for (int ks = 0; ks < 4; ++ks) {
            uint32_t af[4][4];
            const uint32_t asw = ((uint32_t)((2 * ks + a_kga) ^ r7)) << 4;
            #pragma unroll
            for (int mt = 0; mt < 4; ++mt)
                ldsm4(af[mt], Ab + aoff + mt * 2048 + asw);

            uint32_t bf[2][4];
            const uint32_t bsw = ((uint32_t)((2 * ks + b_kga) ^ r7)) << 4;
            #pragma unroll
            for (int np = 0; np < 2; ++np)
                ldsm4(bf[np], Bb + boff + np * 2048 + bsw);

            #pragma unroll
            for (int mt = 0; mt < 4; ++mt)
                #pragma unroll
                for (int np = 0; np < 2; ++np) {
                    mma16(acc[mt][2 * np],     af[mt], bf[np][0], bf[np][1]);
                    mma16(acc[mt][2 * np + 1], af[mt], bf[np][2], bf[np][3]);
                }
        }
        st = (st + 1 >= 3) ? 0 : st + 1;
    }

    // ---- epilogue: demod + store ----
    const int row0 = lane >> 2;
    const int colp = (lane & 3) << 1;
    #pragma unroll
    for (int mt = 0; mt < 4; ++mt) {
        #pragma unroll
        for (int h = 0; h < 2; ++h) {
            const int co = co0 + wm * 64 + mt * 16 + row0 + h * 8;
            const float dm = g_demod[b * COUT + co];
            float* op = out + (size_t)(b * COUT + co) * 4096 + p0 + wn * 32 + colp;
            #pragma unroll
            for (int nt = 0; nt < 4; ++nt) {
                float2 v;
                v.x = acc[mt][nt][2 * h + 0] * dm;
                v.y = acc[mt][nt][2 * h + 1] * dm;
                *(float2*)(op + nt * 8) = v;
            }
        }
    }
}

// ======================= launch =============================================
extern "C" void kernel_launch(void* const* d_in, const int* in_sizes, int n_in,
                              void* d_out, int out_size) {
    const float* x     = (const float*)d_in[0];  // [16,512,64,64]
    const float* style = (const float*)d_in[1];  // [16,512]
    const float* wgt   = (const float*)d_in[2];  // [1,512,512,3,3]
    const float* mw    = (const float*)d_in[3];  // [512,512]
    const float* mb    = (const float*)d_in[4];  // [512]
    float* out = (float*)d_out;                  // [16,512,64,64]

    k_style<<<NB * CIN / 8, 256>>>(style, mw, mb);
    k_wsq<<<(COUT * CIN + 255) / 256, 256>>>(wgt);
    k_demod<<<NB * COUT / 8, 256>>>();
    {
        dim3 g(PW, NB);
        k_padT<<<g, 256>>>(x);
    }
    k_wrh<<<(COUT * KTOT + 255) / 256, 256>>>(wgt);

    cudaFuncSetAttribute(k_conv, cudaFuncAttributeMaxDynamicSharedMemorySize, SM_TOTAL);
    dim3 grid(16, COUT / 128, NB);   // (16 px tiles, 4 co tiles, 16 batch)
    k_conv<<<grid, 512, SM_TOTAL>>>(out);
}

// round 11
// speedup vs baseline: 9.3579x; 1.5461x over previous
#include <cuda_runtime.h>
#include <cuda_fp16.h>
#include <cstdint>

#define NB   16
#define CIN  512
#define COUT 512
#define SDIM 512

#define MOD_SCALE  0.04419417382415922f
#define CONV_SCALE 0.014731391274719742f

#define PW 66
#define KTOT 4608             // CIN*9

// ---------------- scratch (device globals; no allocations allowed) ----------
__device__ float g_s[NB * CIN];
__device__ float g_wsq[COUT * CIN];
__device__ float g_demod[NB * COUT];
// NHWC padded, scaled input, half: [b][py 66][px 66][ci 512]
__device__ __align__(16) __half g_xph[(size_t)NB * PW * PW * CIN];
// weights half, reordered [co][tap*512 + ci]
__device__ __align__(16) __half g_wrh[(size_t)COUT * KTOT];

// ======================= helpers ============================================
__device__ __forceinline__ uint32_t smem_u32(const void* p) {
    uint32_t a;
    asm("{ .reg .u64 t; cvta.to.shared.u64 t, %1; cvt.u32.u64 %0, t; }"
        : "=r"(a) : "l"(p));
    return a;
}
__device__ __forceinline__ void ldsm4(uint32_t* r, uint32_t addr) {
    asm volatile("ldmatrix.sync.aligned.m8n8.x4.shared.b16 {%0,%1,%2,%3}, [%4];"
                 : "=r"(r[0]), "=r"(r[1]), "=r"(r[2]), "=r"(r[3]) : "r"(addr));
}
__device__ __forceinline__ void mma16(float* d, const uint32_t* a,
                                      uint32_t b0, uint32_t b1) {
    asm volatile(
        "mma.sync.aligned.m16n8k16.row.col.f32.f16.f16.f32 "
        "{%0,%1,%2,%3}, {%4,%5,%6,%7}, {%8,%9}, {%0,%1,%2,%3};"
        : "+f"(d[0]), "+f"(d[1]), "+f"(d[2]), "+f"(d[3])
        : "r"(a[0]), "r"(a[1]), "r"(a[2]), "r"(a[3]), "r"(b0), "r"(b1));
}
__device__ __forceinline__ void cp16(uint32_t dst, const void* src) {
    asm volatile("cp.async.cg.shared.global [%0], [%1], 16;"
                 :: "r"(dst), "l"(src) : "memory");
}
#define CP_COMMIT() asm volatile("cp.async.commit_group;" ::: "memory")
#define CP_WAIT1()  asm volatile("cp.async.wait_group 1;" ::: "memory")

// ======================= prep kernels =======================================
__global__ void k_style(const float* __restrict__ style,
                        const float* __restrict__ mw,
                        const float* __restrict__ mb) {
    int w    = blockIdx.x * (blockDim.x >> 5) + (threadIdx.x >> 5);
    int lane = threadIdx.x & 31;
    int b  = w / CIN;
    int ci = w - b * CIN;
    const float* sp = style + b * SDIM;
    const float* wp = mw + ci * SDIM;
    float sum = 0.f;
    for (int d = lane; d < SDIM; d += 32) sum += sp[d] * wp[d];
    #pragma unroll
    for (int o = 16; o; o >>= 1) sum += __shfl_xor_sync(0xffffffffu, sum, o);
    if (lane == 0) g_s[w] = CONV_SCALE * (sum * MOD_SCALE + mb[ci]);
}

__global__ void k_wsq(const float* __restrict__ wgt) {
    int i = blockIdx.x * blockDim.x + threadIdx.x;
    if (i >= COUT * CIN) return;
    const float* p = wgt + i * 9;
    float s = 0.f;
    #pragma unroll
    for (int j = 0; j < 9; ++j) s += p[j] * p[j];
    g_wsq[i] = s;
}

__global__ void k_demod() {
    int w    = blockIdx.x * (blockDim.x >> 5) + (threadIdx.x >> 5);
    int lane = threadIdx.x & 31;
    int b  = w / COUT;
    int co = w - b * COUT;
    const float* wsq = g_wsq + co * CIN;
    const float* sp  = g_s + b * CIN;
    float sum = 0.f;
    for (int ci = lane; ci < CIN; ci += 32) {
        float sv = sp[ci];
        sum += wsq[ci] * sv * sv;
    }
    #pragma unroll
    for (int o = 16; o; o >>= 1) sum += __shfl_xor_sync(0xffffffffu, sum, o);
    if (lane == 0) g_demod[w] = rsqrtf(sum + 1e-8f);
}

// NHWC padded transpose: g_xph[b][py][px][ci] = half(x[b][ci][py-1][px-1]*s)
__global__ __launch_bounds__(256)
void k_padT(const float* __restrict__ x) {
    __shared__ float sm[64][65];
    const int b  = blockIdx.y;
    const int py = blockIdx.x;
    const int tid = threadIdx.x;
    __half* xd = g_xph + (((size_t)b * PW + py) * PW) * CIN;

    if (py == 0 || py == 65) {
        uint4 z = {0, 0, 0, 0};
        for (int i = tid; i < PW * CIN / 8; i += 256)
            ((uint4*)xd)[i] = z;
        return;
    }
    const int y = py - 1;
    for (int i = tid; i < CIN / 2; i += 256) {
        ((__half2*)xd)[i] = __half2(__float2half(0.f), __float2half(0.f));
        ((__half2*)(xd + 65 * CIN))[i] = __half2(__float2half(0.f), __float2half(0.f));
    }
    for (int ci0 = 0; ci0 < CIN; ci0 += 64) {
        __syncthreads();
        for (int i = tid; i < 64 * 64; i += 256) {
            int ci = i >> 6, px = i & 63;
            sm[ci][px] = x[(((size_t)(b * CIN + ci0 + ci) * 64) + y) * 64 + px]
                       * g_s[b * CIN + ci0 + ci];
        }
        __syncthreads();
        for (int i = tid; i < 64 * 32; i += 256) {
            int px = i >> 5, c2 = i & 31;
            __half2 h = __floats2half2_rn(sm[2 * c2][px], sm[2 * c2 + 1][px]);
            *(__half2*)(xd + (size_t)(px + 1) * CIN + ci0 + 2 * c2) = h;
        }
    }
}

// g_wrh[co][tap*512 + ci] = half(W[co][ci][tap])
__global__ void k_wrh(const float* __restrict__ w) {
    int i = blockIdx.x * blockDim.x + threadIdx.x;
    if (i >= COUT * KTOT) return;
    int co  = i / KTOT;
    int r   = i - co * KTOT;
    int tap = r >> 9;
    int ci  = r & 511;
    g_wrh[i] = __float2half_rn(w[(co * 512 + ci) * 9 + tap]);
}

// ======================= main conv kernel ===================================
// CTA 512 thr / 16 warps. Tile M=128 co x N=256 px (4 image rows).
// Outer: ci-group g (8 x 64ci); inner: tap t (9). B = halo tile 6x66 px x 64ci
// (396 x 128B rows) loaded ONCE per g, all 9 taps via shifted ldmatrix rows.
// A = per-chunk 128co x 64ci (16KB), 3 stages (lead 2). One commit per chunk;
// schedule per chunk n: WAIT1 -> barrier -> issue(n+2) -> commit -> compute(n).
// Group G(n) holds exactly A(n); B(g+1) spread over taps 0..7 so its last part
// is in G(9g+9), retired by WAIT1 at its first consuming chunk 9g+9.
#define BROWS 396
#define SM_B0 0
#define SM_B1 50688
#define SM_A0 101376
#define SM_AST 16384
#define SM_TOTAL (SM_A0 + 3 * SM_AST)

__global__ __launch_bounds__(512, 1)
void k_conv(float* __restrict__ out) {
    extern __shared__ char smem[];
    const uint32_t sbase = smem_u32(smem);
    const int tid  = threadIdx.x;
    const int wid  = tid >> 5;
    const int lane = tid & 31;
    const int b    = blockIdx.z;
    const int co0  = blockIdx.y * 128;
    const int p0   = blockIdx.x * 256;   // 4 full image rows
    const int y0   = p0 >> 6;

    const int wm = wid >> 3;             // 0..1 : co offset wm*64
    const int wn = wid & 7;              // 0..7 : px offset wn*32

    const int r7    = lane & 7;
    const int a_row = lane & 15;
    const int a_kga = lane >> 4;
    const int b_row = r7 + (((lane >> 4) & 1) << 3);
    const int b_kga = (lane >> 3) & 1;
    const uint32_t aoff = (uint32_t)(wm * 64 + a_row) * 128;
    // B halo row base per n-tile (warp covers 32 px of one image row)
    const int warp_y = wn >> 1;
    int rbase[2];
    rbase[0] = warp_y * 66 + ((wn & 1) << 5) + b_row;   // np=0
    rbase[1] = rbase[0] + 16;                           // np=1

    const __half* xpb = g_xph + (size_t)b * PW * PW * CIN;
    const __half* wrb = g_wrh + (size_t)co0 * KTOT;

    float acc[4][4][4];
    #pragma unroll
    for (int i = 0; i < 4; ++i)
        #pragma unroll
        for (int j = 0; j < 4; ++j)
            #pragma unroll
            for (int h = 0; h < 4; ++h) acc[i][j][h] = 0.f;

    auto issueA = [&](int g, int tap, int stage) {
        uint32_t Ab = sbase + SM_A0 + stage * SM_AST;
        #pragma unroll
        for (int j = 0; j < 2; ++j) {
            int G   = tid + j * 512;
            int row = G >> 3;
            int c4  = G & 7;
            const __half* src = wrb + (size_t)row * KTOT + tap * 512 + g * 64 + c4 * 8;
            cp16(Ab + row * 128 + (((uint32_t)(c4 ^ (row & 7))) << 4), src);
        }
    };
    auto issueBrow = [&](int g, int row, int c4, uint32_t Bb) {
        int py = row / 66;
        int px = row - py * 66;
        const __half* src = xpb + ((size_t)(y0 + py) * PW + px) * CIN + g * 64 + c4 * 8;
        cp16(Bb + row * 128 + (((uint32_t)(c4 ^ (row & 7))) << 4), src);
    };

    // ---- prologue: G0 = { B(0) full , A(0) }, G1 = { A(1) } ----
    {
        uint32_t Bb0 = sbase + SM_B0;
        #pragma unroll
        for (int i = 0; i < 7; ++i) {
            int G = tid + i * 512;
            if (G < BROWS * 8) issueBrow(0, G >> 3, G & 7, Bb0);
        }
        issueA(0, 0, 0);
        CP_COMMIT();               // G0
        issueA(0, 1, 1);
        CP_COMMIT();               // G1
    }

    int n = 0;
    for (int g = 0; g < 8; ++g) {
        const uint32_t Bb = sbase + ((g & 1) ? SM_B1 : SM_B0);
        for (int t = 0; t < 9; ++t, ++n) {
            CP_WAIT1();        // G(n) retired -> A(n) + needed B parts landed
            __syncthreads();   // cross-thread visibility + WAR for refills

            if (n + 2 < 72) {
                int g2 = (n + 2) / 9;
                int t2 = (n + 2) - 9 * g2;
                issueA(g2, t2, (n + 2) % 3);
            }
            if (g + 1 < 8 && t < 8) {
                int nrows = (t == 7) ? 46 : 50;
                if (tid < nrows * 8) {
                    uint32_t Bn = sbase + (((g + 1) & 1) ? SM_B1 : SM_B0);
                    issueBrow(g + 1, 50 * t + (tid >> 3), tid & 7, Bn);
                }
            }
            CP_COMMIT();       // G(n+2) (possibly empty in tail)

            const uint32_t Ab = sbase + SM_A0 + (n % 3) * SM_AST;
            const int kh = (t >= 6) ? 2 : ((t >= 3) ? 1 : 0);
            const int kw = t - 3 * kh;
            const int rA0 = rbase[0] + kh * 66 + kw;
            const int rA1 = rbase[1] + kh * 66 + kw;

            #pragma unroll
            for (int ks = 0; ks < 4; ++ks) {
                uint32_t af[4][4];
                const uint32_t asw = ((uint32_t)((2 * ks + a_kga) ^ r7)) << 4;
                #pragma unroll
                for (int mt = 0; mt < 4; ++mt)
                    ldsm4(af[mt], Ab + aoff + mt * 2048 + asw);

                uint32_t bf[2][4];
                ldsm4(bf[0], Bb + (uint32_t)rA0 * 128
                           + (((uint32_t)((2 * ks + b_kga) ^ (rA0 & 7))) << 4));
                ldsm4(bf[1], Bb + (uint32_t)rA1 * 128
                           + (((uint32_t)((2 * ks + b_kga) ^ (rA1 & 7))) << 4));

                #pragma unroll
                for (int mt = 0; mt < 4; ++mt)
                    #pragma unroll
                    for (int np = 0; np < 2; ++np) {
                        mma16(acc[mt][2 * np],     af[mt], bf[np][0], bf[np][1]);
                        mma16(acc[mt][2 * np + 1], af[mt], bf[np][2], bf[np][3]);
                    }
            }
        }
    }

    // ---- epilogue: demod + store ----
    const int row0 = lane >> 2;
    const int colp = (lane & 3) << 1;
    #pragma unroll
    for (int mt = 0; mt < 4; ++mt) {
        #pragma unroll
        for (int h = 0; h < 2; ++h) {
            const int co = co0 + wm * 64 + mt * 16 + row0 + h * 8;
            const float dm = g_demod[b * COUT + co];
            float* op = out + (size_t)(b * COUT + co) * 4096 + p0 + wn * 32 + colp;
            #pragma unroll
            for (int nt = 0; nt < 4; ++nt) {
                float2 v;
                v.x = acc[mt][nt][2 * h + 0] * dm;
                v.y = acc[mt][nt][2 * h + 1] * dm;
                *(float2*)(op + nt * 8) = v;
            }
        }
    }
}

// ======================= launch =============================================
extern "C" void kernel_launch(void* const* d_in, const int* in_sizes, int n_in,
                              void* d_out, int out_size) {
    const float* x     = (const float*)d_in[0];  // [16,512,64,64]
    const float* style = (const float*)d_in[1];  // [16,512]
    const float* wgt   = (const float*)d_in[2];  // [1,512,512,3,3]
    const float* mw    = (const float*)d_in[3];  // [512,512]
    const float* mb    = (const float*)d_in[4];  // [512]
    float* out = (float*)d_out;                  // [16,512,64,64]

    k_style<<<NB * CIN / 8, 256>>>(style, mw, mb);
    k_wsq<<<(COUT * CIN + 255) / 256, 256>>>(wgt);
    k_demod<<<NB * COUT / 8, 256>>>();
    {
        dim3 g(PW, NB);
        k_padT<<<g, 256>>>(x);
    }
    k_wrh<<<(COUT * KTOT + 255) / 256, 256>>>(wgt);

    cudaFuncSetAttribute(k_conv, cudaFuncAttributeMaxDynamicSharedMemorySize, SM_TOTAL);
    dim3 grid(16, COUT / 128, NB);   // (16 px tiles, 4 co tiles, 16 batch)
    k_conv<<<grid, 512, SM_TOTAL>>>(out);
}

// round 12
// speedup vs baseline: 9.5009x; 1.0153x over previous
#include <cuda_runtime.h>
#include <cuda_fp16.h>
#include <cstdint>

#define NB   16
#define CIN  512
#define COUT 512
#define SDIM 512

#define MOD_SCALE  0.04419417382415922f
#define CONV_SCALE 0.014731391274719742f

#define PW 66
#define KTOT 4608             // CIN*9

// ---------------- scratch (device globals; no allocations allowed) ----------
__device__ float g_s[NB * CIN];
__device__ float g_wsq[COUT * CIN];
__device__ float g_demod[NB * COUT];
// NHWC padded, scaled input, half: [b][py 66][px 66][ci 512]
__device__ __align__(16) __half g_xph[(size_t)NB * PW * PW * CIN];
// weights half, reordered [co][tap*512 + ci]
__device__ __align__(16) __half g_wrh[(size_t)COUT * KTOT];

// ======================= helpers ============================================
__device__ __forceinline__ uint32_t smem_u32(const void* p) {
    uint32_t a;
    asm("{ .reg .u64 t; cvta.to.shared.u64 t, %1; cvt.u32.u64 %0, t; }"
        : "=r"(a) : "l"(p));
    return a;
}
__device__ __forceinline__ void ldsm4(uint32_t* r, uint32_t addr) {
    asm volatile("ldmatrix.sync.aligned.m8n8.x4.shared.b16 {%0,%1,%2,%3}, [%4];"
                 : "=r"(r[0]), "=r"(r[1]), "=r"(r[2]), "=r"(r[3]) : "r"(addr));
}
__device__ __forceinline__ void mma16(float* d, const uint32_t* a,
                                      uint32_t b0, uint32_t b1) {
    asm volatile(
        "mma.sync.aligned.m16n8k16.row.col.f32.f16.f16.f32 "
        "{%0,%1,%2,%3}, {%4,%5,%6,%7}, {%8,%9}, {%0,%1,%2,%3};"
        : "+f"(d[0]), "+f"(d[1]), "+f"(d[2]), "+f"(d[3])
        : "r"(a[0]), "r"(a[1]), "r"(a[2]), "r"(a[3]), "r"(b0), "r"(b1));
}
__device__ __forceinline__ void cp16(uint32_t dst, const void* src) {
    asm volatile("cp.async.cg.shared.global [%0], [%1], 16;"
                 :: "r"(dst), "l"(src) : "memory");
}
#define CP_COMMIT() asm volatile("cp.async.commit_group;" ::: "memory")
#define CP_WAIT2()  asm volatile("cp.async.wait_group 2;" ::: "memory")

// ======================= prep kernels =======================================
__global__ void k_style(const float* __restrict__ style,
                        const float* __restrict__ mw,
                        const float* __restrict__ mb) {
    int w    = blockIdx.x * (blockDim.x >> 5) + (threadIdx.x >> 5);
    int lane = threadIdx.x & 31;
    int b  = w / CIN;
    int ci = w - b * CIN;
    const float* sp = style + b * SDIM;
    const float* wp = mw + ci * SDIM;
    float sum = 0.f;
    for (int d = lane; d < SDIM; d += 32) sum += sp[d] * wp[d];
    #pragma unroll
    for (int o = 16; o; o >>= 1) sum += __shfl_xor_sync(0xffffffffu, sum, o);
    if (lane == 0) g_s[w] = CONV_SCALE * (sum * MOD_SCALE + mb[ci]);
}

__global__ void k_wsq(const float* __restrict__ wgt) {
    int i = blockIdx.x * blockDim.x + threadIdx.x;
    if (i >= COUT * CIN) return;
    const float* p = wgt + i * 9;
    float s = 0.f;
    #pragma unroll
    for (int j = 0; j < 9; ++j) s += p[j] * p[j];
    g_wsq[i] = s;
}

__global__ void k_demod() {
    int w    = blockIdx.x * (blockDim.x >> 5) + (threadIdx.x >> 5);
    int lane = threadIdx.x & 31;
    int b  = w / COUT;
    int co = w - b * COUT;
    const float* wsq = g_wsq + co * CIN;
    const float* sp  = g_s + b * CIN;
    float sum = 0.f;
    for (int ci = lane; ci < CIN; ci += 32) {
        float sv = sp[ci];
        sum += wsq[ci] * sv * sv;
    }
    #pragma unroll
    for (int o = 16; o; o >>= 1) sum += __shfl_xor_sync(0xffffffffu, sum, o);
    if (lane == 0) g_demod[w] = rsqrtf(sum + 1e-8f);
}

// NHWC padded transpose, split 2x over ci for latency hiding:
// g_xph[b][py][px][ci] = half(x[b][ci][py-1][px-1]*s)
__global__ __launch_bounds__(256)
void k_padT(const float* __restrict__ x) {
    __shared__ float sm[64][65];
    const int b   = blockIdx.y;
    const int py  = blockIdx.x;
    const int cz  = blockIdx.z * 256;      // ci half base (0 or 256)
    const int tid = threadIdx.x;
    __half* xd = g_xph + (((size_t)b * PW + py) * PW) * CIN;

    if (py == 0 || py == 65) {
        uint4 z4 = {0, 0, 0, 0};
        // zero this ci-half for all 66 px: 66 * 32 uint4
        for (int i = tid; i < PW * 32; i += 256) {
            int px = i >> 5, j = i & 31;
            *(uint4*)(xd + (size_t)px * CIN + cz + j * 8) = z4;
        }
        return;
    }
    const int y = py - 1;
    // zero px=0 and px=65 columns in this ci-half
    for (int i = tid; i < 128; i += 256) {
        *(__half2*)(xd + cz + 2 * i) = __half2(__float2half(0.f), __float2half(0.f));
        *(__half2*)(xd + (size_t)65 * CIN + cz + 2 * i)
            = __half2(__float2half(0.f), __float2half(0.f));
    }
    for (int cc = 0; cc < 256; cc += 64) {
        const int ci0 = cz + cc;
        __syncthreads();
        for (int i = tid; i < 64 * 64; i += 256) {
            int ci = i >> 6, px = i & 63;
            sm[ci][px] = x[(((size_t)(b * CIN + ci0 + ci) * 64) + y) * 64 + px]
                       * g_s[b * CIN + ci0 + ci];
        }
        __syncthreads();
        for (int i = tid; i < 64 * 32; i += 256) {
            int px = i >> 5, c2 = i & 31;
            __half2 h = __floats2half2_rn(sm[2 * c2][px], sm[2 * c2 + 1][px]);
            *(__half2*)(xd + (size_t)(px + 1) * CIN + ci0 + 2 * c2) = h;
        }
    }
}

// g_wrh[co][tap*512 + ci] = half(W[co][ci][tap])
__global__ void k_wrh(const float* __restrict__ w) {
    int i = blockIdx.x * blockDim.x + threadIdx.x;
    if (i >= COUT * KTOT) return;
    int co  = i / KTOT;
    int r   = i - co * KTOT;
    int tap = r >> 9;
    int ci  = r & 511;
    g_wrh[i] = __float2half_rn(w[(co * 512 + ci) * 9 + tap]);
}

// ======================= main conv kernel ===================================
// CTA 512 thr / 16 warps. Tile M=128 co x N=256 px (4 image rows).
// Outer: ci-group g (8 x 64ci); inner: tap t (9). B = halo tile 6x66 px x 64ci
// (396 x 128B rows) loaded ONCE per g, all 9 taps via shifted ldmatrix rows.
// A = per-chunk 128co x 64ci (16KB), 4 stages, lead 3. One commit per chunk.
// Per chunk n: WAIT2 -> barrier -> issue A(n+3)/B-part -> commit -> compute(n).
// Ledger: prologue G0={B(0),A0} G1={A1} G2={A2}; iter n commits G(n+3);
// committed at wait = G0..G(n+2); wait_group 2 retires exactly G(n).
// B(g+1) parts at t=0..6 -> G(9g+3..9g+9); first use n=9g+9 retires G(9g+9).
#define BROWS 396
#define SM_B0 0
#define SM_B1 50688
#define SM_A0 101376
#define SM_AST 16384
#define SM_TOTAL (SM_A0 + 4 * SM_AST)

__global__ __launch_bounds__(512, 1)
void k_conv(float* __restrict__ out) {
    extern __shared__ char smem[];
    const uint32_t sbase = smem_u32(smem);
    const int tid  = threadIdx.x;
    const int wid  = tid >> 5;
    const int lane = tid & 31;
    const int b    = blockIdx.z;
    const int co0  = blockIdx.y * 128;
    const int p0   = blockIdx.x * 256;   // 4 full image rows
    const int y0   = p0 >> 6;

    const int wm = wid >> 3;             // 0..1 : co offset wm*64
    const int wn = wid & 7;              // 0..7 : px offset wn*32

    const int r7    = lane & 7;
    const int a_row = lane & 15;
    const int a_kga = lane >> 4;
    const int b_row = r7 + (((lane >> 4) & 1) << 3);
    const int b_kga = (lane >> 3) & 1;
    const uint32_t aoff = (uint32_t)(wm * 64 + a_row) * 128;
    // B halo row base per n-tile (warp covers 32 px of one image row)
    const int warp_y = wn >> 1;
    int rbase[2];
    rbase[0] = warp_y * 66 + ((wn & 1) << 5) + b_row;   // np=0
    rbase[1] = rbase[0] + 16;                           // np=1

    const __half* xpb = g_xph + (size_t)b * PW * PW * CIN;
    const __half* wrb = g_wrh + (size_t)co0 * KTOT;

    float acc[4][4][4];
    #pragma unroll
    for (int i = 0; i < 4; ++i)
        #pragma unroll
        for (int j = 0; j < 4; ++j)
            #pragma unroll
            for (int h = 0; h < 4; ++h) acc[i][j][h] = 0.f;

    auto issueA = [&](int g, int tap, int stage) {
        uint32_t Ab = sbase + SM_A0 + stage * SM_AST;
        #pragma unroll
        for (int j = 0; j < 2; ++j) {
            int G   = tid + j * 512;
            int row = G >> 3;
            int c4  = G & 7;
            const __half* src = wrb + (size_t)row * KTOT + tap * 512 + g * 64 + c4 * 8;
            cp16(Ab + row * 128 + (((uint32_t)(c4 ^ (row & 7))) << 4), src);
        }
    };
    auto issueBrow = [&](int g, int row, int c4, uint32_t Bb) {
        int py = row / 66;
        int px = row - py * 66;
        const __half* src = xpb + ((size_t)(y0 + py) * PW + px) * CIN + g * 64 + c4 * 8;
        cp16(Bb + row * 128 + (((uint32_t)(c4 ^ (row & 7))) << 4), src);
    };

    // ---- prologue: G0 = { B(0) full, A(0) }, G1 = { A(1) }, G2 = { A(2) } ----
    {
        uint32_t Bb0 = sbase + SM_B0;
        #pragma unroll
        for (int i = 0; i < 7; ++i) {
            int G = tid + i * 512;
            if (G < BROWS * 8) issueBrow(0, G >> 3, G & 7, Bb0);
        }
        issueA(0, 0, 0);
        CP_COMMIT();               // G0
        issueA(0, 1, 1);
        CP_COMMIT();               // G1
        issueA(0, 2, 2);
        CP_COMMIT();               // G2
    }

    int n = 0;
    for (int g = 0; g < 8; ++g) {
        const uint32_t Bb = sbase + ((g & 1) ? SM_B1 : SM_B0);
        for (int t = 0; t < 9; ++t, ++n) {
            CP_WAIT2();        // retires G(n): A(n) + any B parts in it landed
            __syncthreads();   // cross-thread visibility + WAR for refills

            if (n + 3 < 72) {
                int g3 = (n + 3) / 9;
                int t3 = (n + 3) - 9 * g3;
                issueA(g3, t3, (n + 3) & 3);
            }
            if (g + 1 < 8 && t < 7) {
                int nrows = (t == 6) ? 54 : 57;
                if (tid < nrows * 8) {
                    uint32_t Bn = sbase + (((g + 1) & 1) ? SM_B1 : SM_B0);
                    issueBrow(g + 1, 57 * t + (tid >> 3), tid & 7, Bn);
                }
            }
            CP_COMMIT();       // G(n+3) (possibly empty in tail)

            const uint32_t Ab = sbase + SM_A0 + (n & 3) * SM_AST;
            const int kh = (t >= 6) ? 2 : ((t >= 3) ? 1 : 0);
            const int kw = t - 3 * kh;
            const int rA0 = rbase[0] + kh * 66 + kw;
            const int rA1 = rbase[1] + kh * 66 + kw;

            #pragma unroll
            for (int ks = 0; ks < 4; ++ks) {
                uint32_t af[4][4];
                const uint32_t asw = ((uint32_t)((2 * ks + a_kga) ^ r7)) << 4;
                #pragma unroll
                for (int mt = 0; mt < 4; ++mt)
                    ldsm4(af[mt], Ab + aoff + mt * 2048 + asw);

                uint32_t bf[2][4];
                ldsm4(bf[0], Bb + (uint32_t)rA0 * 128
                           + (((uint32_t)((2 * ks + b_kga) ^ (rA0 & 7))) << 4));
                ldsm4(bf[1], Bb + (uint32_t)rA1 * 128
                           + (((uint32_t)((2 * ks + b_kga) ^ (rA1 & 7))) << 4));

                #pragma unroll
                for (int mt = 0; mt < 4; ++mt)
                    #pragma unroll
                    for (int np = 0; np < 2; ++np) {
                        mma16(acc[mt][2 * np],     af[mt], bf[np][0], bf[np][1]);
                        mma16(acc[mt][2 * np + 1], af[mt], bf[np][2], bf[np][3]);
                    }
            }
        }
    }

    // ---- epilogue: demod + store ----
    const int row0 = lane >> 2;
    const int colp = (lane & 3) << 1;
    #pragma unroll
    for (int mt = 0; mt < 4; ++mt) {
        #pragma unroll
        for (int h = 0; h < 2; ++h) {
            const int co = co0 + wm * 64 + mt * 16 + row0 + h * 8;
            const float dm = g_demod[b * COUT + co];
            float* op = out + (size_t)(b * COUT + co) * 4096 + p0 + wn * 32 + colp;
            #pragma unroll
            for (int nt = 0; nt < 4; ++nt) {
                float2 v;
                v.x = acc[mt][nt][2 * h + 0] * dm;
                v.y = acc[mt][nt][2 * h + 1] * dm;
                *(float2*)(op + nt * 8) = v;
            }
        }
    }
}

// ======================= launch =============================================
extern "C" void kernel_launch(void* const* d_in, const int* in_sizes, int n_in,
                              void* d_out, int out_size) {
    const float* x     = (const float*)d_in[0];  // [16,512,64,64]
    const float* style = (const float*)d_in[1];  // [16,512]
    const float* wgt   = (const float*)d_in[2];  // [1,512,512,3,3]
    const float* mw    = (const float*)d_in[3];  // [512,512]
    const float* mb    = (const float*)d_in[4];  // [512]
    float* out = (float*)d_out;                  // [16,512,64,64]

    k_style<<<NB * CIN / 8, 256>>>(style, mw, mb);
    k_wsq<<<(COUT * CIN + 255) / 256, 256>>>(wgt);
    k_demod<<<NB * COUT / 8, 256>>>();
    {
        dim3 g(PW, NB, 2);
        k_padT<<<g, 256>>>(x);
    }
    k_wrh<<<(COUT * KTOT + 255) / 256, 256>>>(wgt);

    cudaFuncSetAttribute(k_conv, cudaFuncAttributeMaxDynamicSharedMemorySize, SM_TOTAL);
    dim3 grid(16, COUT / 128, NB);   // (16 px tiles, 4 co tiles, 16 batch)
    k_conv<<<grid, 512, SM_TOTAL>>>(out);
}

// round 13
// speedup vs baseline: 10.0397x; 1.0567x over previous
#include <cuda_runtime.h>
#include <cuda_fp16.h>
#include <cstdint>

#define NB   16
#define CIN  512
#define COUT 512
#define SDIM 512

#define MOD_SCALE  0.04419417382415922f
#define CONV_SCALE 0.014731391274719742f

#define PW 66
#define KTOT 4608             // CIN*9

// ---------------- scratch (device globals; no allocations allowed) ----------
__device__ float g_s[NB * CIN];
__device__ float g_wsq[COUT * CIN];
__device__ float g_demod[NB * COUT];
// NHWC padded, scaled input, half: [b][py 66][px 66][ci 512]
__device__ __align__(16) __half g_xph[(size_t)NB * PW * PW * CIN];
// weights half, reordered [co][tap*512 + ci]
__device__ __align__(16) __half g_wrh[(size_t)COUT * KTOT];

// ======================= helpers ============================================
__device__ __forceinline__ uint32_t smem_u32(const void* p) {
    uint32_t a;
    asm("{ .reg .u64 t; cvta.to.shared.u64 t, %1; cvt.u32.u64 %0, t; }"
        : "=r"(a) : "l"(p));
    return a;
}
__device__ __forceinline__ void ldsm4(uint32_t* r, uint32_t addr) {
    asm volatile("ldmatrix.sync.aligned.m8n8.x4.shared.b16 {%0,%1,%2,%3}, [%4];"
                 : "=r"(r[0]), "=r"(r[1]), "=r"(r[2]), "=r"(r[3]) : "r"(addr));
}
__device__ __forceinline__ void mma16(float* d, const uint32_t* a,
                                      uint32_t b0, uint32_t b1) {
    asm volatile(
        "mma.sync.aligned.m16n8k16.row.col.f32.f16.f16.f32 "
        "{%0,%1,%2,%3}, {%4,%5,%6,%7}, {%8,%9}, {%0,%1,%2,%3};"
        : "+f"(d[0]), "+f"(d[1]), "+f"(d[2]), "+f"(d[3])
        : "r"(a[0]), "r"(a[1]), "r"(a[2]), "r"(a[3]), "r"(b0), "r"(b1));
}
__device__ __forceinline__ void cp16(uint32_t dst, const void* src) {
    asm volatile("cp.async.cg.shared.global [%0], [%1], 16;"
                 :: "r"(dst), "l"(src) : "memory");
}
#define CP_COMMIT() asm volatile("cp.async.commit_group;" ::: "memory")
#define CP_WAIT2()  asm volatile("cp.async.wait_group 2;" ::: "memory")

// ======================= prep kernels =======================================
// fused: blocks [0,1024) -> style GEMM row-warps; blocks [1024,2048) -> wsq
__global__ void k_prep1(const float* __restrict__ style,
                        const float* __restrict__ mw,
                        const float* __restrict__ mb,
                        const float* __restrict__ wgt) {
    if (blockIdx.x < NB * CIN / 8) {
        int w    = blockIdx.x * 8 + (threadIdx.x >> 5);
        int lane = threadIdx.x & 31;
        int b  = w / CIN;
        int ci = w - b * CIN;
        const float* sp = style + b * SDIM;
        const float* wp = mw + ci * SDIM;
        float sum = 0.f;
        for (int d = lane; d < SDIM; d += 32) sum += sp[d] * wp[d];
        #pragma unroll
        for (int o = 16; o; o >>= 1) sum += __shfl_xor_sync(0xffffffffu, sum, o);
        if (lane == 0) g_s[w] = CONV_SCALE * (sum * MOD_SCALE + mb[ci]);
    } else {
        int i = (blockIdx.x - NB * CIN / 8) * 256 + threadIdx.x;
        if (i < COUT * CIN) {
            const float* p = wgt + i * 9;
            float s = 0.f;
            #pragma unroll
            for (int j = 0; j < 9; ++j) s += p[j] * p[j];
            g_wsq[i] = s;
        }
    }
}

__global__ void k_demod() {
    int w    = blockIdx.x * (blockDim.x >> 5) + (threadIdx.x >> 5);
    int lane = threadIdx.x & 31;
    int b  = w / COUT;
    int co = w - b * COUT;
    const float* wsq = g_wsq + co * CIN;
    const float* sp  = g_s + b * CIN;
    float sum = 0.f;
    for (int ci = lane; ci < CIN; ci += 32) {
        float sv = sp[ci];
        sum += wsq[ci] * sv * sv;
    }
    #pragma unroll
    for (int o = 16; o; o >>= 1) sum += __shfl_xor_sync(0xffffffffu, sum, o);
    if (lane == 0) g_demod[w] = rsqrtf(sum + 1e-8f);
}

// NHWC padded transpose, single pass per (b,py):
// g_xph[b][py][px][ci] = half(x[b][ci][py-1][px-1] * g_s[b][ci])
// SMEM: 64px x 256 words (half2), word W = px*256 + ((ci>>1) ^ px).
__global__ __launch_bounds__(512)
void k_padT(const float* __restrict__ x) {
    extern __shared__ __half sm[];           // 64*512 halves = 64KB
    __shared__ float ss[CIN];
    const int b   = blockIdx.y;
    const int py  = blockIdx.x;
    const int tid = threadIdx.x;
    __half* xd = g_xph + (((size_t)b * PW + py) * PW) * CIN;

    if (py == 0 || py == 65) {               // full zero rows
        uint4 z4 = {0, 0, 0, 0};
        for (int i = tid; i < PW * CIN / 8; i += 512)
            ((uint4*)xd)[i] = z4;
        return;
    }
    const int y = py - 1;
    // zero px=0 and px=65 columns (64 uint4 each)
    {
        uint4 z4 = {0, 0, 0, 0};
        if (tid < 128) {
            if (tid < 64) ((uint4*)xd)[tid];
            uint4* dst = (tid < 64) ? ((uint4*)xd) + tid
                                    : ((uint4*)(xd + (size_t)65 * CIN)) + (tid - 64);
            *dst = z4;
        }
    }
    if (tid < CIN) ss[tid] = g_s[b * CIN + tid];
    __syncthreads();

    // load + scale + convert + swizzled SMEM store
    const int px4 = tid & 15;
    const int cib = tid >> 4;                // 0..31
    #pragma unroll 4
    for (int it = 0; it < 16; ++it) {
        const int ci = cib + it * 32;
        const float4 v = *(const float4*)(x + (((size_t)(b * CIN + ci) * 64) + y) * 64 + px4 * 4);
        const float s = ss[ci];
        const int ch = ci >> 1;
        const int cl = ci & 1;
        float vv[4] = {v.x, v.y, v.z, v.w};
        #pragma unroll
        for (int j = 0; j < 4; ++j) {
            int px = px4 * 4 + j;
            sm[px * 512 + (((ch ^ px) << 1) | cl)] = __float2half_rn(vv[j] * s);
        }
    }
    __syncthreads();

    // write out: one 4B word per thread per iter, coalesced 128B/warp
    const uint32_t* smw = (const uint32_t*)sm;
    #pragma unroll 4
    for (int i = tid; i < 64 * 256; i += 512) {
        int px = i >> 8;
        int cw = i & 255;
        uint32_t w = smw[px * 256 + (cw ^ px)];
        *(uint32_t*)(xd + (size_t)(px + 1) * CIN + cw * 2) = w;
    }
}

// g_wrh[co][tap*512 + ci] = half(W[co][ci][tap]) — SMEM transpose per co
__global__ __launch_bounds__(512)
void k_wrh(const float* __restrict__ w) {
    __shared__ float sw[KTOT];               // 18KB
    const int co  = blockIdx.x;
    const int tid = threadIdx.x;
    const float* src = w + (size_t)co * KTOT;
    #pragma unroll
    for (int i = 0; i < 9; ++i)
        sw[tid + i * 512] = src[tid + i * 512];
    __syncthreads();
    __half* dst = g_wrh + (size_t)co * KTOT;
    #pragma unroll
    for (int i = 0; i < 9; ++i) {
        int j   = tid + i * 512;
        int tap = j >> 9;
        int ci  = j & 511;
        dst[j] = __float2half_rn(sw[ci * 9 + tap]);
    }
}

// ======================= main conv kernel ===================================
// CTA 512 thr / 16 warps. Tile M=128 co x N=256 px (4 image rows).
// Outer: ci-group g (8 x 64ci); inner: tap t (9). B = halo tile 6x66 px x 64ci
// (396 x 128B rows) loaded ONCE per g, all 9 taps via shifted ldmatrix rows.
// A = per-chunk 128co x 64ci (16KB), 4 stages, lead 3. One commit per chunk.
// Per chunk n: WAIT2 -> barrier -> issue A(n+3)/B-part -> commit -> compute(n).
#define BROWS 396
#define SM_B0 0
#define SM_B1 50688
#define SM_A0 101376
#define SM_AST 16384
#define SM_TOTAL (SM_A0 + 4 * SM_AST)

__global__ __launch_bounds__(512, 1)
void k_conv(float* __restrict__ out) {
    extern __shared__ char smem[];
    const uint32_t sbase = smem_u32(smem);
    const int tid  = threadIdx.x;
    const int wid  = tid >> 5;
    const int lane = tid & 31;
    const int b    = blockIdx.z;
    const int co0  = blockIdx.y * 128;
    const int p0   = blockIdx.x * 256;   // 4 full image rows
    const int y0   = p0 >> 6;

    const int wm = wid >> 3;             // 0..1 : co offset wm*64
    const int wn = wid & 7;              // 0..7 : px offset wn*32

    const int r7    = lane & 7;
    const int a_row = lane & 15;
    const int a_kga = lane >> 4;
    const int b_row = r7 + (((lane >> 4) & 1) << 3);
    const int b_kga = (lane >> 3) & 1;
    const uint32_t aoff = (uint32_t)(wm * 64 + a_row) * 128;
    const int warp_y = wn >> 1;
    int rbase[2];
    rbase[0] = warp_y * 66 + ((wn & 1) << 5) + b_row;   // np=0
    rbase[1] = rbase[0] + 16;                           // np=1

    const __half* xpb = g_xph + (size_t)b * PW * PW * CIN;
    const __half* wrb = g_wrh + (size_t)co0 * KTOT;

    float acc[4][4][4];
    #pragma unroll
    for (int i = 0; i < 4; ++i)
        #pragma unroll
        for (int j = 0; j < 4; ++j)
            #pragma unroll
            for (int h = 0; h < 4; ++h) acc[i][j][h] = 0.f;

    auto issueA = [&](int g, int tap, int stage) {
        uint32_t Ab = sbase + SM_A0 + stage * SM_AST;
        #pragma unroll
        for (int j = 0; j < 2; ++j) {
            int G   = tid + j * 512;
            int row = G >> 3;
            int c4  = G & 7;
            const __half* src = wrb + (size_t)row * KTOT + tap * 512 + g * 64 + c4 * 8;
            cp16(Ab + row * 128 + (((uint32_t)(c4 ^ (row & 7))) << 4), src);
        }
    };
    auto issueBrow = [&](int g, int row, int c4, uint32_t Bb) {
        int py = row / 66;
        int px = row - py * 66;
        const __half* src = xpb + ((size_t)(y0 + py) * PW + px) * CIN + g * 64 + c4 * 8;
        cp16(Bb + row * 128 + (((uint32_t)(c4 ^ (row & 7))) << 4), src);
    };

    // ---- prologue: G0 = { B(0) full, A(0) }, G1 = { A(1) }, G2 = { A(2) } ----
    {
        uint32_t Bb0 = sbase + SM_B0;
        #pragma unroll
        for (int i = 0; i < 7; ++i) {
            int G = tid + i * 512;
            if (G < BROWS * 8) issueBrow(0, G >> 3, G & 7, Bb0);
        }
        issueA(0, 0, 0);
        CP_COMMIT();               // G0
        issueA(0, 1, 1);
        CP_COMMIT();               // G1
        issueA(0, 2, 2);
        CP_COMMIT();               // G2
    }

    int n = 0;
    for (int g = 0; g < 8; ++g) {
        const uint32_t Bb = sbase + ((g & 1) ? SM_B1 : SM_B0);
        for (int t = 0; t < 9; ++t, ++n) {
            CP_WAIT2();        // retires G(n): A(n) + any B parts in it landed
            __syncthreads();   // cross-thread visibility + WAR for refills

            if (n + 3 < 72) {
                int g3 = (n + 3) / 9;
                int t3 = (n + 3) - 9 * g3;
                issueA(g3, t3, (n + 3) & 3);
            }
            if (g + 1 < 8 && t < 7) {
                int nrows = (t == 6) ? 54 : 57;
                if (tid < nrows * 8) {
                    uint32_t Bn = sbase + (((g + 1) & 1) ? SM_B1 : SM_B0);
                    issueBrow(g + 1, 57 * t + (tid >> 3), tid & 7, Bn);
                }
            }
            CP_COMMIT();       // G(n+3) (possibly empty in tail)

            const uint32_t Ab = sbase + SM_A0 + (n & 3) * SM_AST;
            const int kh = (t >= 6) ? 2 : ((t >= 3) ? 1 : 0);
            const int kw = t - 3 * kh;
            const int rA0 = rbase[0] + kh * 66 + kw;
            const int rA1 = rbase[1] + kh * 66 + kw;

            #pragma unroll
            for (int ks = 0; ks < 4; ++ks) {
                uint32_t af[4][4];
                const uint32_t asw = ((uint32_t)((2 * ks + a_kga) ^ r7)) << 4;
                #pragma unroll
                for (int mt = 0; mt < 4; ++mt)
                    ldsm4(af[mt], Ab + aoff + mt * 2048 + asw);

                uint32_t bf[2][4];
                ldsm4(bf[0], Bb + (uint32_t)rA0 * 128
                           + (((uint32_t)((2 * ks + b_kga) ^ (rA0 & 7))) << 4));
                ldsm4(bf[1], Bb + (uint32_t)rA1 * 128
                           + (((uint32_t)((2 * ks + b_kga) ^ (rA1 & 7))) << 4));

                #pragma unroll
                for (int mt = 0; mt < 4; ++mt)
                    #pragma unroll
                    for (int np = 0; np < 2; ++np) {
                        mma16(acc[mt][2 * np],     af[mt], bf[np][0], bf[np][1]);
                        mma16(acc[mt][2 * np + 1], af[mt], bf[np][2], bf[np][3]);
                    }
            }
        }
    }

    // ---- epilogue: demod + store ----
    const int row0 = lane >> 2;
    const int colp = (lane & 3) << 1;
    #pragma unroll
    for (int mt = 0; mt < 4; ++mt) {
        #pragma unroll
        for (int h = 0; h < 2; ++h) {
            const int co = co0 + wm * 64 + mt * 16 + row0 + h * 8;
            const float dm = g_demod[b * COUT + co];
            float* op = out + (size_t)(b * COUT + co) * 4096 + p0 + wn * 32 + colp;
            #pragma unroll
            for (int nt = 0; nt < 4; ++nt) {
                float2 v;
                v.x = acc[mt][nt][2 * h + 0] * dm;
                v.y = acc[mt][nt][2 * h + 1] * dm;
                *(float2*)(op + nt * 8) = v;
            }
        }
    }
}

// ======================= launch =============================================
extern "C" void kernel_launch(void* const* d_in, const int* in_sizes, int n_in,
                              void* d_out, int out_size) {
    const float* x     = (const float*)d_in[0];  // [16,512,64,64]
    const float* style = (const float*)d_in[1];  // [16,512]
    const float* wgt   = (const float*)d_in[2];  // [1,512,512,3,3]
    const float* mw    = (const float*)d_in[3];  // [512,512]
    const float* mb    = (const float*)d_in[4];  // [512]
    float* out = (float*)d_out;                  // [16,512,64,64]

    k_prep1<<<NB * CIN / 8 + (COUT * CIN + 255) / 256, 256>>>(style, mw, mb, wgt);
    k_demod<<<NB * COUT / 8, 256>>>();
    {
        cudaFuncSetAttribute(k_padT, cudaFuncAttributeMaxDynamicSharedMemorySize,
                             64 * 512 * 2);
        dim3 g(PW, NB);
        k_padT<<<g, 512, 64 * 512 * 2>>>(x);
    }
    k_wrh<<<COUT, 512>>>(wgt);

    cudaFuncSetAttribute(k_conv, cudaFuncAttributeMaxDynamicSharedMemorySize, SM_TOTAL);
    dim3 grid(16, COUT / 128, NB);   // (16 px tiles, 4 co tiles, 16 batch)
    k_conv<<<grid, 512, SM_TOTAL>>>(out);
}